// round 11
// baseline (speedup 1.0000x reference)
#include <cuda_runtime.h>

typedef unsigned long long u64;

#define D      32
#define KNN    4
#define WARPS  8
#define SPB    128       // samples per block; lane owns lane+{0,32,64,96}
#define TILE   32
#define SHARD  256       // 2048 / 8 warps, exactly 8 tiles of 32

// ---------------- packed f32x2 helpers (sm_103a FFMA2 path) ----------------
__device__ __forceinline__ u64 fma2(u64 a, u64 b, u64 c) {
    u64 r;
    asm("fma.rn.f32x2 %0, %1, %2, %3;" : "=l"(r) : "l"(a), "l"(b), "l"(c));
    return r;
}
__device__ __forceinline__ u64 add2(u64 a, u64 b) {
    u64 r;
    asm("add.rn.f32x2 %0, %1, %2;" : "=l"(r) : "l"(a), "l"(b));
    return r;
}
__device__ __forceinline__ void unpack2(u64 a, float& lo, float& hi) {
    asm("mov.b64 {%0, %1}, %2;" : "=f"(lo), "=f"(hi) : "l"(a));
}
__device__ __forceinline__ u64 pack2(float a, float b) {
    u64 r;
    asm("mov.b64 %0, {%1, %2};" : "=l"(r) : "f"(a), "f"(b));
    return r;
}

// ---------------- scratch: per-center squared norms ----------------
__device__ float g_cnorm[4096];

__global__ void cnorm_kernel(const float* __restrict__ ctrs, int n_fcns) {
    int f = blockIdx.x * blockDim.x + threadIdx.x;
    if (f < n_fcns) {
        const float4* c4 = (const float4*)(ctrs + (size_t)f * D);
        float s = 0.0f;
#pragma unroll
        for (int j = 0; j < D / 4; j++) {
            float4 q = __ldg(c4 + j);
            s += q.x * q.x + q.y * q.y + q.z * q.z + q.w * q.w;
        }
        g_cnorm[f] = s;
    }
}

// select-only stable top-4 insert; SAFE when sc >= d3 (no-op). Strict <.
#define INS4(sc, f, d0, d1, d2, d3, i0, i1, i2, i3) do {                        \
    bool h0 = (sc) < d0, h1 = (sc) < d1, h2 = (sc) < d2, h3 = (sc) < d3;        \
    float n3 = h3 ? (h2 ? d2 : (sc)) : d3;  int m3 = h3 ? (h2 ? i2 : (f)) : i3; \
    float n2 = h2 ? (h1 ? d1 : (sc)) : d2;  int m2 = h2 ? (h1 ? i1 : (f)) : i2; \
    float n1 = h1 ? (h0 ? d0 : (sc)) : d1;  int m1 = h1 ? (h0 ? i0 : (f)) : i1; \
    d0 = h0 ? (sc) : d0;                    i0 = h0 ? (f) : i0;                 \
    d1 = n1; i1 = m1; d2 = n2; i2 = m2; d3 = n3; i3 = m3;                       \
} while (0)

// per-sample score: 2 chains of 8 fma2, acc0 seeded with (cnorm, 0)
#define DOT2(xp, cnp, out) do {                                                 \
    u64 p0 = (cnp), p1 = 0ull;                                                  \
    p0 = fma2((xp)[0],  cc[0],  p0);  p1 = fma2((xp)[1],  cc[1],  p1);          \
    p0 = fma2((xp)[2],  cc[2],  p0);  p1 = fma2((xp)[3],  cc[3],  p1);          \
    p0 = fma2((xp)[4],  cc[4],  p0);  p1 = fma2((xp)[5],  cc[5],  p1);          \
    p0 = fma2((xp)[6],  cc[6],  p0);  p1 = fma2((xp)[7],  cc[7],  p1);          \
    p0 = fma2((xp)[8],  cc[8],  p0);  p1 = fma2((xp)[9],  cc[9],  p1);          \
    p0 = fma2((xp)[10], cc[10], p0);  p1 = fma2((xp)[11], cc[11], p1);          \
    p0 = fma2((xp)[12], cc[12], p0);  p1 = fma2((xp)[13], cc[13], p1);          \
    p0 = fma2((xp)[14], cc[14], p0);  p1 = fma2((xp)[15], cc[15], p1);          \
    u64 rr = add2(p0, p1);                                                      \
    float lo, hi; unpack2(rr, lo, hi);                                          \
    (out) = lo + hi;                                                            \
} while (0)

// ---------------- main fused kernel ----------------
// Block = 256 threads = 8 warps, 128 samples. Lane owns 4 samples
// (lane + {0,32,64,96}), so each center broadcast serves 128 scores/warp.
// Phase A: warp w scans centers [w*256, (w+1)*256) in 8 exact tiles of 32.
// 32 candidates/sample merged lexicographically. Phase B: 16 samples/warp.
__global__ __launch_bounds__(256, 1) void pwl_kernel(
    const float* __restrict__ x,
    const float* __restrict__ ctrs,
    const float* __restrict__ wts,
    const float* __restrict__ offs,
    float* __restrict__ y,
    int n_fcns)
{
    extern __shared__ __align__(16) char smem[];
    float* s_ctr = (float*)smem;                               // [8][32*32]
    float* s_cn  = (float*)(smem + WARPS * TILE * D * 4);      // [8][32]
    float* s_x   = s_cn + WARPS * TILE;                        // [128][33]
    float* s_cd  = s_x + SPB * (D + 1);                        // [128][32]
    int*   s_ci  = (int*)(s_cd + SPB * WARPS * KNN);           // [128][32]
    int*   s_idx = s_ci + SPB * WARPS * KNN;                   // [128][4]

    const int lane = threadIdx.x & 31;
    const int w    = threadIdx.x >> 5;
    const int r0   = blockIdx.x * SPB + lane;

    // ---- load 4 sample rows: regs hold packed (-2*x); warp 0 stores raw x ----
    u64 xp0[16], xp1[16], xp2[16], xp3[16];
    {
        const float4* g0 = (const float4*)(x + (size_t)r0 * D);
        const float4* g1 = (const float4*)(x + (size_t)(r0 + 32) * D);
        const float4* g2 = (const float4*)(x + (size_t)(r0 + 64) * D);
        const float4* g3 = (const float4*)(x + (size_t)(r0 + 96) * D);
#pragma unroll
        for (int j = 0; j < 8; j++) {
            float4 q0 = __ldg(g0 + j);
            float4 q1 = __ldg(g1 + j);
            float4 q2 = __ldg(g2 + j);
            float4 q3 = __ldg(g3 + j);
            if (w == 0) {
                float* d0 = s_x + (lane)      * (D + 1) + 4 * j;
                float* d1 = s_x + (lane + 32) * (D + 1) + 4 * j;
                float* d2 = s_x + (lane + 64) * (D + 1) + 4 * j;
                float* d3 = s_x + (lane + 96) * (D + 1) + 4 * j;
                d0[0] = q0.x; d0[1] = q0.y; d0[2] = q0.z; d0[3] = q0.w;
                d1[0] = q1.x; d1[1] = q1.y; d1[2] = q1.z; d1[3] = q1.w;
                d2[0] = q2.x; d2[1] = q2.y; d2[2] = q2.z; d2[3] = q2.w;
                d3[0] = q3.x; d3[1] = q3.y; d3[2] = q3.z; d3[3] = q3.w;
            }
            xp0[2 * j] = pack2(-2.0f * q0.x, -2.0f * q0.y);
            xp0[2 * j + 1] = pack2(-2.0f * q0.z, -2.0f * q0.w);
            xp1[2 * j] = pack2(-2.0f * q1.x, -2.0f * q1.y);
            xp1[2 * j + 1] = pack2(-2.0f * q1.z, -2.0f * q1.w);
            xp2[2 * j] = pack2(-2.0f * q2.x, -2.0f * q2.y);
            xp2[2 * j + 1] = pack2(-2.0f * q2.z, -2.0f * q2.w);
            xp3[2 * j] = pack2(-2.0f * q3.x, -2.0f * q3.y);
            xp3[2 * j + 1] = pack2(-2.0f * q3.z, -2.0f * q3.w);
        }
    }

    const int fstart = w * SHARD;
    float* my_ctr = s_ctr + w * TILE * D;
    float* my_cn  = s_cn + w * TILE;

    float A0 = 3.4e38f, A1 = 3.4e38f, A2 = 3.4e38f, A3 = 3.4e38f;
    float B0 = 3.4e38f, B1 = 3.4e38f, B2 = 3.4e38f, B3 = 3.4e38f;
    float C0 = 3.4e38f, C1 = 3.4e38f, C2 = 3.4e38f, C3 = 3.4e38f;
    float E0 = 3.4e38f, E1 = 3.4e38f, E2 = 3.4e38f, E3 = 3.4e38f;
    int Ai0 = 0, Ai1 = 0, Ai2 = 0, Ai3 = 0;
    int Bi0 = 0, Bi1 = 0, Bi2 = 0, Bi3 = 0;
    int Ci0 = 0, Ci1 = 0, Ci2 = 0, Ci3 = 0;
    int Ei0 = 0, Ei1 = 0, Ei2 = 0, Ei3 = 0;

    const float4* cg4 = (const float4*)ctrs;

    for (int t = fstart; t < fstart + SHARD; t += TILE) {
        __syncwarp();
        // stage 32 centers for this warp (exact tiles, no guards)
#pragma unroll
        for (int i = 0; i < 8; i++) {
            int e = i * 32 + lane;                             // 0..255
            ((float4*)my_ctr)[e] = __ldg(cg4 + (size_t)(t + (e >> 3)) * 8 + (e & 7));
        }
        my_cn[lane] = g_cnorm[t + lane];
        __syncwarp();

        for (int ff = 0; ff < TILE; ff++) {
            const u64* cc = (const u64*)(my_ctr + ff * D);     // 16 x LDS.64/128
            u64 cnp = (u64)__float_as_uint(my_cn[ff]);          // (cnorm, 0)
            float sA, sB, sC, sE;
            DOT2(xp0, cnp, sA);
            DOT2(xp1, cnp, sB);
            DOT2(xp2, cnp, sC);
            DOT2(xp3, cnp, sE);
            const int f = t + ff;
            if (sA < A3 || sB < B3 || sC < C3 || sE < E3) {    // rare after warmup
                INS4(sA, f, A0, A1, A2, A3, Ai0, Ai1, Ai2, Ai3);
                INS4(sB, f, B0, B1, B2, B3, Bi0, Bi1, Bi2, Bi3);
                INS4(sC, f, C0, C1, C2, C3, Ci0, Ci1, Ci2, Ci3);
                INS4(sE, f, E0, E1, E2, E3, Ei0, Ei1, Ei2, Ei3);
            }
        }
    }

    // ---- publish candidates (32 per sample), merge 32 -> 4 ----
    {
        float* cd;
        int*   ci;
        cd = s_cd + (lane) * (WARPS * KNN) + w * KNN;
        ci = s_ci + (lane) * (WARPS * KNN) + w * KNN;
        cd[0] = A0; cd[1] = A1; cd[2] = A2; cd[3] = A3;
        ci[0] = Ai0; ci[1] = Ai1; ci[2] = Ai2; ci[3] = Ai3;
        cd = s_cd + (lane + 32) * (WARPS * KNN) + w * KNN;
        ci = s_ci + (lane + 32) * (WARPS * KNN) + w * KNN;
        cd[0] = B0; cd[1] = B1; cd[2] = B2; cd[3] = B3;
        ci[0] = Bi0; ci[1] = Bi1; ci[2] = Bi2; ci[3] = Bi3;
        cd = s_cd + (lane + 64) * (WARPS * KNN) + w * KNN;
        ci = s_ci + (lane + 64) * (WARPS * KNN) + w * KNN;
        cd[0] = C0; cd[1] = C1; cd[2] = C2; cd[3] = C3;
        ci[0] = Ci0; ci[1] = Ci1; ci[2] = Ci2; ci[3] = Ci3;
        cd = s_cd + (lane + 96) * (WARPS * KNN) + w * KNN;
        ci = s_ci + (lane + 96) * (WARPS * KNN) + w * KNN;
        cd[0] = E0; cd[1] = E1; cd[2] = E2; cd[3] = E3;
        ci[0] = Ei0; ci[1] = Ei1; ci[2] = Ei2; ci[3] = Ei3;
    }
    __syncthreads();

    if (threadIdx.x < SPB) {
        const int ms = threadIdx.x;
        float cd[WARPS * KNN];
        int   ci[WARPS * KNN];
#pragma unroll
        for (int j = 0; j < WARPS * KNN; j++) {
            cd[j] = s_cd[ms * (WARPS * KNN) + j];
            ci[j] = s_ci[ms * (WARPS * KNN) + j];
        }
#pragma unroll
        for (int k = 0; k < KNN; k++) {
            int best = 0;
#pragma unroll
            for (int j = 1; j < WARPS * KNN; j++) {
                // lexicographic (dist, idx): matches top_k tie-break
                if (cd[j] < cd[best] || (cd[j] == cd[best] && ci[j] < ci[best]))
                    best = j;
            }
            s_idx[ms * KNN + k] = ci[best];
            cd[best] = 3.4e38f;
        }
    }
    __syncthreads();

    // ---- phase B: warp-cooperative apply, 16 samples per warp ----
    // lane = (prow = lane>>3 in 0..3, e4 = lane&7): covers d in {prow, prow+4, ...}
    // and output columns [4*e4, 4*e4+4).
    const int prow = lane >> 3;
    const int e4   = lane & 7;
    const float4* offs4 = (const float4*)offs;

    for (int sb = w; sb < SPB; sb += WARPS) {
        float4 acc = make_float4(0.f, 0.f, 0.f, 0.f);
#pragma unroll
        for (int k = 0; k < KNN; k++) {
            int f = s_idx[sb * KNN + k];
            const float4* w4 = (const float4*)(wts + (size_t)f * D * D);
            const float*  cf = ctrs + (size_t)f * D;
#pragma unroll
            for (int dd = 0; dd < 8; dd++) {
                int d = dd * 4 + prow;
                float4 wv = __ldg(w4 + d * 8 + e4);
                float  xc = s_x[sb * (D + 1) + d] - __ldg(cf + d);
                acc.x = fmaf(xc, wv.x, acc.x);
                acc.y = fmaf(xc, wv.y, acc.y);
                acc.z = fmaf(xc, wv.z, acc.z);
                acc.w = fmaf(xc, wv.w, acc.w);
            }
        }
#pragma unroll
        for (int off = 8; off < 32; off <<= 1) {
            acc.x += __shfl_xor_sync(0xffffffffu, acc.x, off);
            acc.y += __shfl_xor_sync(0xffffffffu, acc.y, off);
            acc.z += __shfl_xor_sync(0xffffffffu, acc.z, off);
            acc.w += __shfl_xor_sync(0xffffffffu, acc.w, off);
        }
        if (prow == 0) {
#pragma unroll
            for (int k = 0; k < KNN; k++) {
                int f = s_idx[sb * KNN + k];
                float4 ov = __ldg(offs4 + f * 8 + e4);
                acc.x += ov.x; acc.y += ov.y; acc.z += ov.z; acc.w += ov.w;
            }
            ((float4*)(y + (size_t)(blockIdx.x * SPB + sb) * D))[e4] = acc;
        }
    }
}

// ---------------- launch ----------------
#define DYN_SMEM (WARPS * TILE * D * 4 + WARPS * TILE * 4 + SPB * (D + 1) * 4 \
                  + SPB * WARPS * KNN * 8 + SPB * KNN * 4)

extern "C" void kernel_launch(void* const* d_in, const int* in_sizes, int n_in,
                              void* d_out, int out_size)
{
    const float* x    = (const float*)d_in[0];
    const float* ctrs = (const float*)d_in[1];
    const float* wts  = (const float*)d_in[2];
    const float* offs = (const float*)d_in[3];
    float* y = (float*)d_out;

    int n_smps = in_sizes[0] / D;
    int n_fcns = in_sizes[1] / D;

    cudaFuncSetAttribute(pwl_kernel,
                         cudaFuncAttributeMaxDynamicSharedMemorySize, DYN_SMEM);

    cnorm_kernel<<<(n_fcns + 255) / 256, 256>>>(ctrs, n_fcns);
    pwl_kernel<<<n_smps / SPB, 256, DYN_SMEM>>>(x, ctrs, wts, offs, y, n_fcns);
}